// round 4
// baseline (speedup 1.0000x reference)
#include <cuda_runtime.h>
#include <math.h>

#define NB      4
#define NGRID   512
#define NTARGET 1024
#define NBASIS  5
#define NCH     8

#define SPLIT   16                // NGRID split factor
#define CHUNK   (NGRID / SPLIT)   // 32 grid points per block
#define TILES   16                // target tiles per batch (64 targets each)
#define TPT     4                 // targets per thread

// Partial sums: [SPLIT][NB][NTARGET][NCH]  (2 MB device scratch, L2-resident)
__device__ float d_part[SPLIT * NB * NTARGET * NCH];
// Per-(b,tile) completion tickets; finisher resets to 0 each launch.
__device__ int d_cnt[NB * TILES];

// ---------------------------------------------------------------------------
// One kernel: each block = (batch b, target tile of 64, grid chunk of 32).
// 128 threads: warp w covers channels {2w,2w+1}; lanes 0-15 -> c0, 16-31 -> c1;
// each thread handles 4 targets. Last block of each (b,tile) group reduces the
// SPLIT partials (fixed order -> deterministic) and writes out = g_b + sum.
// ---------------------------------------------------------------------------
__global__ void __launch_bounds__(128)
finallayer_onepass(const float* __restrict__ x_grid,    // [NB][NGRID][NCH]
                   const float* __restrict__ h_grid,    // [NB][NGRID][NBASIS][NCH]
                   const float* __restrict__ target_x,  // [NB][NTARGET][NCH]
                   const float* __restrict__ sigma,     // [NBASIS][NCH]
                   const float* __restrict__ g_w,       // [1][NBASIS]
                   const float* __restrict__ g_b,       // [1]
                   float* __restrict__ out)             // [NB][NTARGET][NCH]
{
    __shared__ __align__(16) float2 pairs[NCH][CHUNK];  // (x*sc0, hsum0)
    __shared__ float s_sc[NCH][NBASIS];
    __shared__ int   s_grp[NCH][NBASIS];
    __shared__ int   s_nu[NCH];
    __shared__ float s_gw[NBASIS];
    __shared__ int   s_last;

    const int tid   = threadIdx.x;
    const int chunk = blockIdx.x & (SPLIT - 1);
    const int tile  = (blockIdx.x >> 4) & (TILES - 1);
    const int b     = blockIdx.x >> 8;            // blockIdx = b*256 + tile*16 + chunk
    const int g0    = chunk * CHUNK;

    // --- per-channel scale dedup (redundant per block, trivial) ---
    if (tid < NCH) {
        const float C = 0.8493218002880190f;      // sqrt(0.5 * log2(e))
        float s[NBASIS], uniq[NBASIS];
        int nu = 0;
#pragma unroll
        for (int k = 0; k < NBASIS; ++k)
            s[k] = expf(sigma[k * NCH + tid]) + 1e-6f;
#pragma unroll
        for (int k = 0; k < NBASIS; ++k) {
            int u = -1;
            for (int j = 0; j < nu; ++j)
                if (uniq[j] == s[k]) { u = j; break; }
            if (u < 0) { u = nu; uniq[nu++] = s[k]; }
            s_grp[tid][k] = u;
        }
        s_nu[tid] = nu;
        for (int u = 0; u < nu; ++u) s_sc[tid][u] = C / uniq[u];
    } else if (tid < NCH + NBASIS) {
        s_gw[tid - NCH] = g_w[tid - NCH];
    }
    __syncthreads();

    // --- fill chunk: x pre-scaled by sc0, hsum0 folded from h*g_w ---
    const float* xg = x_grid + (b * NGRID + g0) * NCH;
    const float* hg = h_grid + (b * NGRID + g0) * NBASIS * NCH;
    for (int i = tid; i < CHUNK * NCH; i += 128) {
        const int c = i & 7, g = i >> 3;
        float acc = 0.f;
#pragma unroll
        for (int k = 0; k < NBASIS; ++k)
            if (s_grp[c][k] == 0)
                acc += hg[(g * NBASIS + k) * NCH + c] * s_gw[k];
        pairs[c][g] = make_float2(xg[i] * s_sc[c][0], acc);
    }
    __syncthreads();

    // --- main loop: 4 targets per thread, 2 grid points per LDS.128 ---
    const int lane = tid & 31;
    const int c    = ((tid >> 5) << 1) | (lane >> 4);
    const int tb   = tile * 64 + (lane & 15);     // targets tb + 16*j

    float ts[TPT], acc[TPT];
#pragma unroll
    for (int j = 0; j < TPT; ++j) {
        float tv = __ldg(&target_x[(b * NTARGET + tb + 16 * j) * NCH + c]);
        ts[j]  = tv * s_sc[c][0];
        acc[j] = 0.f;
    }

    const float4* pc = (const float4*)&pairs[c][0];
#pragma unroll 8
    for (int gg = 0; gg < CHUNK / 2; ++gg) {
        float4 q = pc[gg];                        // (x0*sc, h0, x1*sc, h1)
#pragma unroll
        for (int j = 0; j < TPT; ++j) {
            float d0 = q.x - ts[j];
            float d1 = q.z - ts[j];
            float a0 = -d0 * d0;
            float a1 = -d1 * d1;
            float w0, w1;
            asm("ex2.approx.ftz.f32 %0, %1;" : "=f"(w0) : "f"(a0));
            asm("ex2.approx.ftz.f32 %0, %1;" : "=f"(w1) : "f"(a1));
            acc[j] = fmaf(w0, q.y, acc[j]);
            acc[j] = fmaf(w1, q.w, acc[j]);
        }
    }

    // --- generic cold path: extra unique scales (not taken for uniform sigma) ---
    const int nu = s_nu[c];
    for (int u = 1; u < nu; ++u) {
        const float sc = s_sc[c][u];
        for (int g = 0; g < CHUNK; ++g) {
            float xv = __ldg(&xg[g * NCH + c]);
            float hv = 0.f;
#pragma unroll
            for (int k = 0; k < NBASIS; ++k)
                if (s_grp[c][k] == u)
                    hv += __ldg(&hg[(g * NBASIS + k) * NCH + c]) * s_gw[k];
            float xs = xv * sc;
#pragma unroll
            for (int j = 0; j < TPT; ++j) {
                float tvs = __ldg(&target_x[(b * NTARGET + tb + 16 * j) * NCH + c]) * sc;
                float ds  = xs - tvs;
                float a   = -ds * ds;
                float w;
                asm("ex2.approx.ftz.f32 %0, %1;" : "=f"(w) : "f"(a));
                acc[j] = fmaf(w, hv, acc[j]);
            }
        }
    }

    // --- publish partials ---
#pragma unroll
    for (int j = 0; j < TPT; ++j)
        d_part[((chunk * NB + b) * NTARGET + tb + 16 * j) * NCH + c] = acc[j];

    // --- ticket: last block of this (b,tile) group reduces & writes out ---
    __threadfence();                              // release partials
    __syncthreads();
    if (tid == 0)
        s_last = (atomicAdd(&d_cnt[b * TILES + tile], 1) == SPLIT - 1);
    __syncthreads();

    if (s_last) {
        __threadfence();                          // acquire others' partials
        const float bias = __ldg(g_b);
#pragma unroll
        for (int j = 0; j < TPT; ++j) {
            const int t = tb + 16 * j;
            float sum = bias;
#pragma unroll
            for (int s = 0; s < SPLIT; ++s)       // fixed order -> deterministic
                sum += d_part[((s * NB + b) * NTARGET + t) * NCH + c];
            out[(b * NTARGET + t) * NCH + c] = sum;
        }
        if (tid == 0)
            atomicExch(&d_cnt[b * TILES + tile], 0);  // reset for next launch
    }
}

// ---------------------------------------------------------------------------
extern "C" void kernel_launch(void* const* d_in, const int* in_sizes, int n_in,
                              void* d_out, int out_size) {
    const float* x_grid   = (const float*)d_in[0];  // [4,512,8]
    const float* h_grid   = (const float*)d_in[1];  // [4,512,5,8]
    const float* target_x = (const float*)d_in[2];  // [4,1024,8]
    const float* sigma    = (const float*)d_in[3];  // [5,8]
    const float* g_w      = (const float*)d_in[4];  // [1,5]
    const float* g_b      = (const float*)d_in[5];  // [1]
    float* out = (float*)d_out;                     // [4,1024,8]

    finallayer_onepass<<<NB * TILES * SPLIT, 128>>>(
        x_grid, h_grid, target_x, sigma, g_w, g_b, out);
}

// round 6
// speedup vs baseline: 1.1225x; 1.1225x over previous
#include <cuda_runtime.h>
#include <cstdint>
#include <math.h>

#define NB      4
#define NGRID   512
#define NTARGET 1024
#define NBASIS  5
#define NCH     8

#define CSIZE   8                 // cluster size = grid-chunk split
#define CHUNK   (NGRID / CSIZE)   // 64 grid points per CTA
#define TILES   16                // target tiles per batch (64 targets each)
#define TPT     4                 // targets per thread

// ld.shared::cluster from peer CTA's smem
__device__ __forceinline__ float dsmem_ld(unsigned int local_addr, unsigned int rank) {
    unsigned int rem; float v;
    asm("mapa.shared::cluster.u32 %0, %1, %2;" : "=r"(rem) : "r"(local_addr), "r"(rank));
    asm("ld.shared::cluster.f32 %0, [%1];" : "=f"(v) : "r"(rem));
    return v;
}

// ---------------------------------------------------------------------------
// One kernel, clusters of 8 CTAs. Cluster = (batch b, tile of 64 targets);
// CTA rank r owns grid chunk r (64 points). 128 threads: warp w covers
// channels {2w,2w+1}, lanes 0-15 -> c0, 16-31 -> c1, TPT=4 targets/thread.
// Partials land in each CTA's smem; after barrier.cluster each CTA reduces
// its 1/8 output slice via DSMEM reads (fixed rank order -> deterministic).
// ---------------------------------------------------------------------------
__global__ void __launch_bounds__(128) __cluster_dims__(CSIZE, 1, 1)
finallayer_cluster(const float* __restrict__ x_grid,    // [NB][NGRID][NCH]
                   const float* __restrict__ h_grid,    // [NB][NGRID][NBASIS][NCH]
                   const float* __restrict__ target_x,  // [NB][NTARGET][NCH]
                   const float* __restrict__ sigma,     // [NBASIS][NCH]
                   const float* __restrict__ g_w,       // [1][NBASIS]
                   const float* __restrict__ g_b,       // [1]
                   float* __restrict__ out)             // [NB][NTARGET][NCH]
{
    __shared__ __align__(16) float2 pairs[NCH][CHUNK];  // (x*sc0, hsum0), 4 KB
    __shared__ float s_part[64 * NCH];                  // partials, o = t_local*8+c
    __shared__ float s_sc[NCH][NBASIS];
    __shared__ int   s_grp[NCH][NBASIS];
    __shared__ int   s_nu[NCH];
    __shared__ float s_gw[NBASIS];

    const int tid   = threadIdx.x;
    const int chunk = blockIdx.x & (CSIZE - 1);   // == cluster ctarank
    const int tile  = (blockIdx.x >> 3) & (TILES - 1);
    const int b     = blockIdx.x >> 7;            // blockIdx = b*128 + tile*8 + chunk
    const int g0    = chunk * CHUNK;

    // --- per-channel scale dedup (redundant per CTA, trivial) ---
    if (tid < NCH) {
        const float C = 0.8493218002880190f;      // sqrt(0.5 * log2(e))
        float s[NBASIS], uniq[NBASIS];
        int nu = 0;
#pragma unroll
        for (int k = 0; k < NBASIS; ++k)
            s[k] = expf(sigma[k * NCH + tid]) + 1e-6f;
#pragma unroll
        for (int k = 0; k < NBASIS; ++k) {
            int u = -1;
            for (int j = 0; j < nu; ++j)
                if (uniq[j] == s[k]) { u = j; break; }
            if (u < 0) { u = nu; uniq[nu++] = s[k]; }
            s_grp[tid][k] = u;
        }
        s_nu[tid] = nu;
        for (int u = 0; u < nu; ++u) s_sc[tid][u] = C / uniq[u];
    } else if (tid < NCH + NBASIS) {
        s_gw[tid - NCH] = g_w[tid - NCH];
    }
    __syncthreads();

    // --- fill chunk: x pre-scaled by sc0, hsum0 folded from h*g_w ---
    const float* xg = x_grid + (b * NGRID + g0) * NCH;
    const float* hg = h_grid + (b * NGRID + g0) * NBASIS * NCH;
    for (int i = tid; i < CHUNK * NCH; i += 128) {
        const int c = i & 7, g = i >> 3;
        float acc = 0.f;
#pragma unroll
        for (int k = 0; k < NBASIS; ++k)
            if (s_grp[c][k] == 0)
                acc += hg[(g * NBASIS + k) * NCH + c] * s_gw[k];
        pairs[c][g] = make_float2(xg[i] * s_sc[c][0], acc);
    }
    __syncthreads();

    // --- main loop: 4 targets/thread, 2 grid points per LDS.128 ---
    const int lane = tid & 31;
    const int c    = ((tid >> 5) << 1) | (lane >> 4);
    const int tb   = tile * 64 + (lane & 15);     // targets tb + 16*j

    float ts[TPT], acc[TPT];
#pragma unroll
    for (int j = 0; j < TPT; ++j) {
        float tv = __ldg(&target_x[(b * NTARGET + tb + 16 * j) * NCH + c]);
        ts[j]  = tv * s_sc[c][0];
        acc[j] = 0.f;
    }

    const float4* pc = (const float4*)&pairs[c][0];
#pragma unroll 8
    for (int gg = 0; gg < CHUNK / 2; ++gg) {
        float4 q = pc[gg];                        // (x0*sc, h0, x1*sc, h1)
#pragma unroll
        for (int j = 0; j < TPT; ++j) {
            float d0 = q.x - ts[j];
            float d1 = q.z - ts[j];
            float a0 = -d0 * d0;
            float a1 = -d1 * d1;
            float w0, w1;
            asm("ex2.approx.ftz.f32 %0, %1;" : "=f"(w0) : "f"(a0));
            asm("ex2.approx.ftz.f32 %0, %1;" : "=f"(w1) : "f"(a1));
            acc[j] = fmaf(w0, q.y, acc[j]);
            acc[j] = fmaf(w1, q.w, acc[j]);
        }
    }

    // --- generic cold path: extra unique scales (not taken for uniform sigma) ---
    const int nu = s_nu[c];
    for (int u = 1; u < nu; ++u) {
        const float sc = s_sc[c][u];
        for (int g = 0; g < CHUNK; ++g) {
            float xv = __ldg(&xg[g * NCH + c]);
            float hv = 0.f;
#pragma unroll
            for (int k = 0; k < NBASIS; ++k)
                if (s_grp[c][k] == u)
                    hv += __ldg(&hg[(g * NBASIS + k) * NCH + c]) * s_gw[k];
            float xs = xv * sc;
#pragma unroll
            for (int j = 0; j < TPT; ++j) {
                float tvs = __ldg(&target_x[(b * NTARGET + tb + 16 * j) * NCH + c]) * sc;
                float ds  = xs - tvs;
                float a   = -ds * ds;
                float w;
                asm("ex2.approx.ftz.f32 %0, %1;" : "=f"(w) : "f"(a));
                acc[j] = fmaf(w, hv, acc[j]);
            }
        }
    }

    // --- stash partials: s_part[t_local*8 + c] ---
#pragma unroll
    for (int j = 0; j < TPT; ++j)
        s_part[((lane & 15) + 16 * j) * NCH + c] = acc[j];

    // --- cluster barrier (arrive=release, wait=acquire) ---
    asm volatile("barrier.cluster.arrive.aligned;" ::: "memory");
    asm volatile("barrier.cluster.wait.aligned;"   ::: "memory");

    // --- each CTA reduces its 1/8 slice of the 512 tile outputs ---
    if (tid < 64) {
        const int o = chunk * 64 + tid;           // t_local*8 + c, 64 per CTA
        const unsigned int la =
            (unsigned int)__cvta_generic_to_shared(&s_part[o]);
        float sum = __ldg(g_b);
#pragma unroll
        for (int r = 0; r < CSIZE; ++r)           // fixed order -> deterministic
            sum += dsmem_ld(la, (unsigned int)r);
        out[(b * NTARGET + tile * 64) * NCH + o] = sum;  // coalesced
    }

    // no CTA may exit while peers still read its smem
    asm volatile("barrier.cluster.arrive.aligned;" ::: "memory");
    asm volatile("barrier.cluster.wait.aligned;"   ::: "memory");
}

// ---------------------------------------------------------------------------
extern "C" void kernel_launch(void* const* d_in, const int* in_sizes, int n_in,
                              void* d_out, int out_size) {
    const float* x_grid   = (const float*)d_in[0];  // [4,512,8]
    const float* h_grid   = (const float*)d_in[1];  // [4,512,5,8]
    const float* target_x = (const float*)d_in[2];  // [4,1024,8]
    const float* sigma    = (const float*)d_in[3];  // [5,8]
    const float* g_w      = (const float*)d_in[4];  // [1,5]
    const float* g_b      = (const float*)d_in[5];  // [1]
    float* out = (float*)d_out;                     // [4,1024,8]

    finallayer_cluster<<<NB * TILES * CSIZE, 128>>>(
        x_grid, h_grid, target_x, sigma, g_w, g_b, out);
}

// round 8
// speedup vs baseline: 1.1253x; 1.0025x over previous
#include <cuda_runtime.h>
#include <cstdint>
#include <math.h>

#define NB      4
#define NGRID   512
#define NTARGET 1024
#define NBASIS  5
#define NCH     8

#define NCHUNK  8                 // grid chunks per CTA (one per warp quad)
#define CHUNK   (NGRID / NCHUNK)  // 64 grid points
#define TILES   64                // 16-target tiles per batch
#define ROWF2   (NGRID + 2)       // padded row stride (float2) -> conflict-free

// ---------------------------------------------------------------------------
// Single kernel, no cross-CTA traffic. CTA = 1024 threads = 32 warps,
// one CTA per (batch, 16-target tile), grid = 256.
//   warp w: grid chunk = w>>2, channel pair = w&3
//   lane:   c = 2*(w&3) + (lane>>4), t_local = lane&15  (1 target/thread)
// Full (x*sc0, hsum0) table in smem, shared by all warps; 8 chunk partials
// reduced intra-CTA through smem (fixed order -> deterministic).
// ---------------------------------------------------------------------------
__global__ void __launch_bounds__(1024)
finallayer_big(const float* __restrict__ x_grid,    // [NB][NGRID][NCH]
               const float* __restrict__ h_grid,    // [NB][NGRID][NBASIS][NCH]
               const float* __restrict__ target_x,  // [NB][NTARGET][NCH]
               const float* __restrict__ sigma,     // [NBASIS][NCH]
               const float* __restrict__ g_w,       // [1][NBASIS]
               const float* __restrict__ g_b,       // [1]
               float* __restrict__ out)             // [NB][NTARGET][NCH]
{
    __shared__ __align__(16) float2 pairs[NCH * ROWF2];  // (x*sc0, hsum0) ~32 KB
    __shared__ float s_part[NCHUNK][16 * NCH];           // chunk partials, 4 KB
    __shared__ float s_sc[NCH][NBASIS];
    __shared__ int   s_grp[NCH][NBASIS];
    __shared__ int   s_nu[NCH];
    __shared__ float s_gw[NBASIS];

    const int tid  = threadIdx.x;
    const int tile = blockIdx.x & (TILES - 1);
    const int b    = blockIdx.x >> 6;

    // --- per-channel scale dedup (redundant per CTA, trivial) ---
    if (tid < NCH) {
        const float C = 0.8493218002880190f;  // sqrt(0.5 * log2(e))
        float s[NBASIS], uniq[NBASIS];
        int nu = 0;
#pragma unroll
        for (int k = 0; k < NBASIS; ++k)
            s[k] = expf(sigma[k * NCH + tid]) + 1e-6f;
#pragma unroll
        for (int k = 0; k < NBASIS; ++k) {
            int u = -1;
            for (int j = 0; j < nu; ++j)
                if (uniq[j] == s[k]) { u = j; break; }
            if (u < 0) { u = nu; uniq[nu++] = s[k]; }
            s_grp[tid][k] = u;
        }
        s_nu[tid] = nu;
        for (int u = 0; u < nu; ++u) s_sc[tid][u] = C / uniq[u];
    } else if (tid < NCH + NBASIS) {
        s_gw[tid - NCH] = g_w[tid - NCH];
    }
    __syncthreads();

    // --- fill full table: x pre-scaled by sc0, hsum0 folded from h*g_w ---
    const float* xg = x_grid + b * (NGRID * NCH);
    const float* hg = h_grid + b * (NGRID * NBASIS * NCH);
#pragma unroll
    for (int i = tid; i < NGRID * NCH; i += 1024) {
        const int c = i & 7, g = i >> 3;
        float acc = 0.f;
#pragma unroll
        for (int k = 0; k < NBASIS; ++k)
            if (s_grp[c][k] == 0)
                acc += hg[(g * NBASIS + k) * NCH + c] * s_gw[k];
        pairs[c * ROWF2 + g] = make_float2(xg[i] * s_sc[c][0], acc);
    }
    __syncthreads();

    // --- main loop: each warp = (chunk, channel pair); 1 target/thread ---
    const int w     = tid >> 5;
    const int lane  = tid & 31;
    const int chunk = w >> 2;
    const int c     = ((w & 3) << 1) | (lane >> 4);
    const int tl    = lane & 15;                 // local target 0..15
    const int t     = tile * 16 + tl;

    const float tv = __ldg(&target_x[(b * NTARGET + t) * NCH + c]);
    const float ts = tv * s_sc[c][0];
    float acc = 0.f;

    const float4* pc = (const float4*)(pairs + c * ROWF2) + chunk * (CHUNK / 2);
#pragma unroll 8
    for (int gg = 0; gg < CHUNK / 2; ++gg) {
        float4 q = pc[gg];                       // (x0*sc, h0, x1*sc, h1)
        float d0 = q.x - ts;
        float d1 = q.z - ts;
        float a0 = -d0 * d0;
        float a1 = -d1 * d1;
        float w0, w1;
        asm("ex2.approx.ftz.f32 %0, %1;" : "=f"(w0) : "f"(a0));
        asm("ex2.approx.ftz.f32 %0, %1;" : "=f"(w1) : "f"(a1));
        acc = fmaf(w0, q.y, acc);
        acc = fmaf(w1, q.w, acc);
    }

    // --- generic cold path: extra unique scales (not taken for uniform sigma) ---
    const int nu = s_nu[c];
    const int g0 = chunk * CHUNK;
    for (int u = 1; u < nu; ++u) {
        const float sc  = s_sc[c][u];
        const float nts = -tv * sc;
        for (int g = 0; g < CHUNK; ++g) {
            float xv = __ldg(&xg[(g0 + g) * NCH + c]);
            float hv = 0.f;
#pragma unroll
            for (int k = 0; k < NBASIS; ++k)
                if (s_grp[c][k] == u)
                    hv += __ldg(&hg[((g0 + g) * NBASIS + k) * NCH + c]) * s_gw[k];
            float ds = fmaf(xv, sc, nts);
            float a  = -ds * ds;
            float wv;
            asm("ex2.approx.ftz.f32 %0, %1;" : "=f"(wv) : "f"(a));
            acc = fmaf(wv, hv, acc);
        }
    }

    // --- intra-CTA reduction over the 8 chunks ---
    s_part[chunk][tl * NCH + c] = acc;
    __syncthreads();

    if (tid < 16 * NCH) {                        // tid = t_local*8 + c
        float sum = __ldg(g_b);
#pragma unroll
        for (int s = 0; s < NCHUNK; ++s)         // fixed order -> deterministic
            sum += s_part[s][tid];
        out[(b * NTARGET + tile * 16) * NCH + tid] = sum;  // coalesced
    }
}

// ---------------------------------------------------------------------------
extern "C" void kernel_launch(void* const* d_in, const int* in_sizes, int n_in,
                              void* d_out, int out_size) {
    const float* x_grid   = (const float*)d_in[0];  // [4,512,8]
    const float* h_grid   = (const float*)d_in[1];  // [4,512,5,8]
    const float* target_x = (const float*)d_in[2];  // [4,1024,8]
    const float* sigma    = (const float*)d_in[3];  // [5,8]
    const float* g_w      = (const float*)d_in[4];  // [1,5]
    const float* g_b      = (const float*)d_in[5];  // [1]
    float* out = (float*)d_out;                     // [4,1024,8]

    finallayer_big<<<NB * TILES, 1024>>>(
        x_grid, h_grid, target_x, sigma, g_w, g_b, out);
}